// round 14
// baseline (speedup 1.0000x reference)
#include <cuda_runtime.h>
#include <cuda_bf16.h>
#include <cuda_fp16.h>
#include <cstdint>

// Problem constants
#define NB   64
#define NT   1000
#define NN   512
#define NI   512
#define NM   (NB*NT)

#define ZS_ELEMS   (NB*NT*NN)
#define ST_STRIDE  ((NT+1)*NN)

// ---------------------------------------------------------------------------
// Scratch (device globals — no allocation allowed)
// g_curh layout: row m = b*NT + t  (same as R10 best)
// ---------------------------------------------------------------------------
__device__ __align__(16) __half g_curh[(size_t)NM * NN];
__device__ float  g_Rt[NN * NN];
__device__ __align__(16) __half g_wh[NN * NI];

// ---------------------------------------------------------------------------
// Portable PTX helpers (sm_80+ only — tcgen05 unavailable at compute_103)
// ---------------------------------------------------------------------------
__device__ __forceinline__ uint32_t smem_to_u32(const void* p) {
    uint32_t a;
    asm("{ .reg .u64 t; cvta.to.shared.u64 t, %1; cvt.u32.u64 %0, t; }" : "=r"(a) : "l"(p));
    return a;
}
__device__ __forceinline__ void cp_async16(uint32_t dst, const void* src) {
    asm volatile("cp.async.cg.shared.global [%0], [%1], 16;" :: "r"(dst), "l"(src) : "memory");
}
__device__ __forceinline__ void ldsm_x4(uint32_t r[4], uint32_t addr) {
    asm volatile("ldmatrix.sync.aligned.m8n8.x4.shared.b16 {%0,%1,%2,%3}, [%4];"
        : "=r"(r[0]), "=r"(r[1]), "=r"(r[2]), "=r"(r[3]) : "r"(addr));
}
__device__ __forceinline__ void mma16816f(float d[4], const uint32_t a[4], const uint32_t b[2]) {
    asm volatile("mma.sync.aligned.m16n8k16.row.col.f32.f16.f16.f32 "
        "{%0,%1,%2,%3}, {%4,%5,%6,%7}, {%8,%9}, {%0,%1,%2,%3};"
        : "+f"(d[0]), "+f"(d[1]), "+f"(d[2]), "+f"(d[3])
        : "r"(a[0]), "r"(a[1]), "r"(a[2]), "r"(a[3]), "r"(b[0]), "r"(b[1]));
}
#define SWZ(off) ((off) ^ (((off) >> 3) & 0x70))

// ---------------------------------------------------------------------------
// prep_all: transpose R (blocks 0-255) + convert W -> f16 (blocks 256-511).
// x is NOT converted here anymore — the GEMM stages fp32 x and converts in smem.
// ---------------------------------------------------------------------------
#define TR_BLOCKS 256
#define W_BLOCKS  ((NN * NI / 4) / 256)  // 256
__global__ __launch_bounds__(256) void prep_all(const float* __restrict__ R,
                                                const float* __restrict__ W) {
    int blk = blockIdx.x;
    if (blk < TR_BLOCKS) {
        __shared__ float tile[32][33];
        int bx = (blk & 15) * 32, by = (blk >> 4) * 32;
        int tx = threadIdx.x & 31, ty8 = threadIdx.x >> 5;
#pragma unroll
        for (int r = 0; r < 4; r++) {
            int y = ty8 + r * 8;
            tile[y][tx] = R[(by + y) * NN + bx + tx];
        }
        __syncthreads();
#pragma unroll
        for (int r = 0; r < 4; r++) {
            int y = ty8 + r * 8;
            g_Rt[(bx + y) * NN + (by + tx)] = tile[tx][y];
        }
    } else {
        int i = (blk - TR_BLOCKS) * 256 + threadIdx.x;
        float4 v = ((const float4*)W)[i];
        ushort4 o;
        o.x = __half_as_ushort(__float2half_rn(v.x));
        o.y = __half_as_ushort(__float2half_rn(v.y));
        o.z = __half_as_ushort(__float2half_rn(v.z));
        o.w = __half_as_ushort(__float2half_rn(v.w));
        ((ushort4*)g_wh)[i] = o;
    }
}

// ---------------------------------------------------------------------------
// f16 GEMM with integrated x-conversion: curh = f16(f16(X)*Wh + bias).
// CTA 128x64 tile, 4 warps (2m x 2n), BK=64, 2-stage cp.async pipeline.
// SMEM: A32 stages 2x32KB (fp32 x rows, 256B/row, granule swizzle j^(r&15)),
//       B stages 2x8KB (f16 Wh rows, 128B/row, SWZ), Af16 16KB (converted A,
//       128B/row, SWZ — identical layout to the previous ldmatrix path).
// Per chunk: wait -> bar1 -> issue loads(c+1) -> convert A32(c)->Af16 -> bar2
//            -> ldmatrix + MMA.
// ---------------------------------------------------------------------------
#define BK        64
#define NCHUNK    (NI / BK)      // 8
#define A32_STAGE 32768          // 128 rows x 256B
#define B_STAGE   8192           // 64 rows x 128B
#define AF16_OFF  (2 * A32_STAGE + 2 * B_STAGE)   // 81920
#define GEMM_SMEM (AF16_OFF + 16384)              // 98304 (96KB)

__global__ __launch_bounds__(128, 2) void gemm_tc(const float* __restrict__ x,
                                                  const float* __restrict__ bias) {
    extern __shared__ char smem[];
    uint32_t sb = smem_to_u32(smem);
    const int tid = threadIdx.x, lane = tid & 31, wid = tid >> 5;
    const int m0 = blockIdx.y * 128, n0 = blockIdx.x * 64;
    const int wm = (wid & 1) * 64;
    const int wn = (wid >> 1) * 32;

    float acc[4][4][4];
#pragma unroll
    for (int i = 0; i < 4; i++)
#pragma unroll
        for (int j = 0; j < 4; j++)
#pragma unroll
            for (int k = 0; k < 4; k++) acc[i][j][k] = 0.f;

    // loaders: thread t owns A row t (fp32, from x directly);
    // threads 0-63 own B row t (f16 from g_wh).
    const float* pX = x + (size_t)(m0 + tid) * NI;
    const bool hasB = (tid < 64);
    const __half* pB = g_wh + (size_t)(n0 + (tid & 63)) * NI;
    const int swz16 = tid & 15;   // A32 granule swizzle key

    auto load_chunk = [&](int c) {
        int s = c & 1;
        uint32_t a32 = sb + (uint32_t)s * A32_STAGE + (uint32_t)tid * 256;
        const float* px = pX + c * BK;
#pragma unroll
        for (int j = 0; j < 16; j++)
            cp_async16(a32 + (uint32_t)((j ^ swz16) << 4), px + j * 4);
        if (hasB) {
            uint32_t bb = sb + 2 * A32_STAGE + (uint32_t)s * B_STAGE;
            const __half* pb = pB + c * BK;
#pragma unroll
            for (int j = 0; j < 8; j++)
                cp_async16(bb + SWZ((uint32_t)((tid & 63) * 128 + j * 16)), pb + j * 8);
        }
        asm volatile("cp.async.commit_group;" ::: "memory");
    };

    const int a_row = wm + (lane & 15);
    const int a_cb  = (lane >> 4) * 16;
    const int b_row = wn + (lane & 7) + ((lane >> 4) * 8);
    const int b_cb  = ((lane >> 3) & 1) * 16;

    load_chunk(0);

    for (int c = 0; c < NCHUNK; c++) {
        asm volatile("cp.async.wait_group 0;" ::: "memory");  // chunk c landed (this thread)
        __syncthreads();  // everyone's chunk-c data visible; compute of c-1 done

        if (c + 1 < NCHUNK) load_chunk(c + 1);   // overlaps convert+compute of c

        // convert A32(c) row tid -> Af16 (same SWZ layout ldmatrix expects)
        {
            uint32_t a32off = (uint32_t)(c & 1) * A32_STAGE + (uint32_t)tid * 256;
            uint32_t dstrow = (uint32_t)tid * 128;
#pragma unroll
            for (int j = 0; j < 16; j++) {
                float4 v = *(const float4*)(smem + a32off + ((j ^ swz16) << 4));
                __half2* dst = (__half2*)(smem + AF16_OFF + SWZ(dstrow + (uint32_t)j * 8));
                dst[0] = __floats2half2_rn(v.x, v.y);
                dst[1] = __floats2half2_rn(v.z, v.w);
            }
        }
        __syncthreads();  // Af16 ready for all warps

        uint32_t af16 = sb + AF16_OFF;
        uint32_t bbase = sb + 2 * A32_STAGE + (uint32_t)(c & 1) * B_STAGE;
#pragma unroll
        for (int kk = 0; kk < 4; kk++) {
            uint32_t ah[4][4], bh[4][2];
#pragma unroll
            for (int mt = 0; mt < 4; mt++) {
                uint32_t off = (uint32_t)((a_row + mt * 16) * 128 + kk * 32 + a_cb);
                ldsm_x4(ah[mt], af16 + SWZ(off));
            }
#pragma unroll
            for (int p = 0; p < 2; p++) {
                uint32_t off = (uint32_t)((b_row + p * 16) * 128 + kk * 32 + b_cb);
                uint32_t t4[4];
                ldsm_x4(t4, bbase + SWZ(off));
                bh[2 * p][0] = t4[0]; bh[2 * p][1] = t4[1];
                bh[2 * p + 1][0] = t4[2]; bh[2 * p + 1][1] = t4[3];
            }
#pragma unroll
            for (int mt = 0; mt < 4; mt++)
#pragma unroll
                for (int nt = 0; nt < 4; nt++)
                    mma16816f(acc[mt][nt], ah[mt], bh[nt]);
        }
    }

    // Epilogue: +bias, convert to f16, store half2
    const int erow = m0 + wm + (lane >> 2);
    const int ecol0 = n0 + wn + (lane & 3) * 2;
    float2 brg[4];
#pragma unroll
    for (int nt = 0; nt < 4; nt++)
        brg[nt] = *(const float2*)(bias + ecol0 + nt * 8);
#pragma unroll
    for (int mt = 0; mt < 4; mt++) {
        int r0 = erow + mt * 16;
#pragma unroll
        for (int nt = 0; nt < 4; nt++) {
            __half2 h0 = __floats2half2_rn(acc[mt][nt][0] + brg[nt].x,
                                           acc[mt][nt][1] + brg[nt].y);
            __half2 h1 = __floats2half2_rn(acc[mt][nt][2] + brg[nt].x,
                                           acc[mt][nt][3] + brg[nt].y);
            *(__half2*)(g_curh + (size_t)r0 * NN + ecol0 + nt * 8) = h0;
            *(__half2*)(g_curh + (size_t)(r0 + 8) * NN + ecol0 + nt * 8) = h1;
        }
    }
}

// ---------------------------------------------------------------------------
// ALIF scan (R10 best): 128 CTAs (2 per batch, stream-split), 512 threads,
// 1 neuron/thread, speculative 8-step windows, ballot path on spikes.
// ---------------------------------------------------------------------------
__global__ __launch_bounds__(512) void alif_scan(const float* __restrict__ beta,
                                                 const float* __restrict__ beta2,
                                                 const float* __restrict__ decay_v,
                                                 const float* __restrict__ decay_b,
                                                 float* __restrict__ out) {
    const int b = blockIdx.x >> 1;
    const int p = blockIdx.x & 1;
    const int tid = threadIdx.x;
    const int w = tid >> 5, lane = tid & 31;

    __shared__ uint32_t zmask[16];
    __shared__ int act[NN];

    const float be = beta[tid];
    const float b2 = beta2[tid];
    const float dv = decay_v[tid];
    const float db = decay_b[tid];
    const float omdv = 1.f - dv;
    const float omdb = 1.f - db;

    float v = 0.f, bb = 0.f, zp = 0.f;
    int nact = 0;

    const __half* cur = g_curh + (size_t)b * NT * NN + tid;
    const float*  Rto = g_Rt + tid;

    float* zsb = out + (size_t)b * NT * NN + tid;
    float* vf  = out + ZS_ELEMS + (size_t)(0 * NB + b) * ST_STRIDE + tid;
    float* zf  = out + ZS_ELEMS + (size_t)(1 * NB + b) * ST_STRIDE + tid;
    float* bf  = out + ZS_ELEMS + (size_t)(2 * NB + b) * ST_STRIDE + tid;

    if (p == 0) {
        vf[0] = 0.f;
    } else {
        zf[0] = 0.f;
        bf[0] = 0.f;
    }

    __half cpre[8];
#pragma unroll
    for (int i = 0; i < 8; i++) cpre[i] = cur[(size_t)i * NN];

    auto slow_window = [&](int tb) {
        for (int u = 0; u < 8; u++) {
            const int t = tb + u;
            float c = __half2float(cur[(size_t)t * NN]);

            float rec = 0.f;
            for (int k = 0; k < nact; k++) rec += Rto[(size_t)act[k] * NN];

            v *= (1.f - zp);
            float vt = dv * v + omdv * ((c + rec) - bb);
            float zt = (vt >= 1.0f) ? 1.f : 0.f;
            bb = db * bb + omdb * (be * vt + b2 * zt);
            v = vt; zp = zt;

            size_t tpo = (size_t)(t + 1) * NN;
            if (p == 0) {
                zsb[(size_t)t * NN] = zt;
                vf[tpo] = vt;
            } else {
                zf[tpo] = zt;
                bf[tpo] = bb;
            }

            uint32_t m = __ballot_sync(0xffffffffu, zt != 0.f);
            if (lane == 0) zmask[w] = m;
            __syncthreads();
            int myoff = 0, tot = 0;
#pragma unroll
            for (int i = 0; i < 16; i++) {
                int pc = __popc(zmask[i]);
                if (i < w) myoff += pc;
                tot += pc;
            }
            if (zt != 0.f) {
                int rank = __popc(m & ((1u << lane) - 1u));
                act[myoff + rank] = tid;
            }
            nact = tot;
            __syncthreads();
        }
#pragma unroll
        for (int u = 0; u < 8; u++) {
            int tp = tb + 8 + u;
            if (tp < NT) cpre[u] = cur[(size_t)tp * NN];
        }
    };

    for (int tb = 0; tb < NT; tb += 8) {
        if (nact == 0) {
            const float v0 = v, bb0 = bb;
            int spec = 0;
#pragma unroll
            for (int u = 0; u < 8; u++) {
                const int t = tb + u;
                float c = __half2float(cpre[u]);
                if (t + 8 < NT) cpre[u] = cur[(size_t)(t + 8) * NN];

                float vt = dv * v + omdv * (c - bb);
                float zt = (vt >= 1.0f) ? 1.f : 0.f;
                spec |= (zt != 0.f);
                bb = db * bb + omdb * (be * vt + b2 * zt);
                v = vt;

                size_t tpo = (size_t)(t + 1) * NN;
                if (p == 0) {
                    zsb[(size_t)t * NN] = zt;
                    vf[tpo] = vt;
                } else {
                    zf[tpo] = zt;
                    bf[tpo] = bb;
                }
            }
            int flag = __syncthreads_count(spec);
            if (flag) {
                v = v0; bb = bb0; zp = 0.f; nact = 0;
                slow_window(tb);
            } else {
                zp = 0.f; nact = 0;
            }
        } else {
            slow_window(tb);
        }
    }
}

// ---------------------------------------------------------------------------
extern "C" void kernel_launch(void* const* d_in, const int* in_sizes, int n_in,
                              void* d_out, int out_size) {
    const float* x     = (const float*)d_in[0];
    const float* W     = (const float*)d_in[1];
    const float* bias  = (const float*)d_in[2];
    const float* R     = (const float*)d_in[3];
    const float* beta  = (const float*)d_in[4];
    const float* beta2 = (const float*)d_in[5];
    const float* dvp   = (const float*)d_in[6];
    const float* dbp   = (const float*)d_in[7];
    float* out = (float*)d_out;

    cudaFuncSetAttribute(gemm_tc, cudaFuncAttributeMaxDynamicSharedMemorySize, GEMM_SMEM);

    prep_all<<<TR_BLOCKS + W_BLOCKS, 256>>>(R, W);

    dim3 ggrid(NN / 64, NM / 128);   // (8, 500), n fastest
    gemm_tc<<<ggrid, 128, GEMM_SMEM>>>(x, bias);

    alif_scan<<<2 * NB, 512>>>(beta, beta2, dvp, dbp, out);
}

// round 15
// speedup vs baseline: 1.3847x; 1.3847x over previous
#include <cuda_runtime.h>
#include <cuda_bf16.h>
#include <cuda_fp16.h>
#include <cstdint>

// Problem constants
#define NB   64
#define NT   1000
#define NN   512
#define NI   512
#define NM   (NB*NT)

#define ZS_ELEMS   (NB*NT*NN)
#define ST_STRIDE  ((NT+1)*NN)

// ---------------------------------------------------------------------------
// Scratch (device globals — no allocation allowed)
// g_curh layout: row m = b*NT + t
// ---------------------------------------------------------------------------
__device__ __align__(16) __half g_curh[(size_t)NM * NN];
__device__ float  g_Rt[NN * NN];
__device__ __align__(16) __half g_xh[(size_t)NM * NI];
__device__ __align__(16) __half g_wh[NN * NI];

// ---------------------------------------------------------------------------
// Portable PTX helpers (sm_80+ only — tcgen05 unavailable at compute_103)
// ---------------------------------------------------------------------------
__device__ __forceinline__ uint32_t smem_to_u32(const void* p) {
    uint32_t a;
    asm("{ .reg .u64 t; cvta.to.shared.u64 t, %1; cvt.u32.u64 %0, t; }" : "=r"(a) : "l"(p));
    return a;
}
__device__ __forceinline__ void cp_async16(uint32_t dst, const void* src) {
    asm volatile("cp.async.cg.shared.global [%0], [%1], 16;" :: "r"(dst), "l"(src) : "memory");
}
__device__ __forceinline__ void ldsm_x4(uint32_t r[4], uint32_t addr) {
    asm volatile("ldmatrix.sync.aligned.m8n8.x4.shared.b16 {%0,%1,%2,%3}, [%4];"
        : "=r"(r[0]), "=r"(r[1]), "=r"(r[2]), "=r"(r[3]) : "r"(addr));
}
__device__ __forceinline__ void mma16816f(float d[4], const uint32_t a[4], const uint32_t b[2]) {
    asm volatile("mma.sync.aligned.m16n8k16.row.col.f32.f16.f16.f32 "
        "{%0,%1,%2,%3}, {%4,%5,%6,%7}, {%8,%9}, {%0,%1,%2,%3};"
        : "+f"(d[0]), "+f"(d[1]), "+f"(d[2]), "+f"(d[3])
        : "r"(a[0]), "r"(a[1]), "r"(a[2]), "r"(a[3]), "r"(b[0]), "r"(b[1]));
}
#define SWZ(off) ((off) ^ (((off) >> 3) & 0x70))

// ---------------------------------------------------------------------------
// prep_all: transpose R + convert W -> f16 + convert x -> f16 (R10 version).
// ---------------------------------------------------------------------------
#define TR_BLOCKS 256
#define W_BLOCKS  ((NN * NI / 4) / 256)  // 256
#define X_BLOCKS  ((NM * NI / 4) / 256)  // 32768
__global__ __launch_bounds__(256) void prep_all(const float* __restrict__ R,
                                                const float* __restrict__ W,
                                                const float* __restrict__ x) {
    int blk = blockIdx.x;
    if (blk < TR_BLOCKS) {
        __shared__ float tile[32][33];
        int bx = (blk & 15) * 32, by = (blk >> 4) * 32;
        int tx = threadIdx.x & 31, ty8 = threadIdx.x >> 5;
#pragma unroll
        for (int r = 0; r < 4; r++) {
            int y = ty8 + r * 8;
            tile[y][tx] = R[(by + y) * NN + bx + tx];
        }
        __syncthreads();
#pragma unroll
        for (int r = 0; r < 4; r++) {
            int y = ty8 + r * 8;
            g_Rt[(bx + y) * NN + (by + tx)] = tile[tx][y];
        }
    } else if (blk < TR_BLOCKS + W_BLOCKS) {
        int i = (blk - TR_BLOCKS) * 256 + threadIdx.x;
        float4 v = ((const float4*)W)[i];
        ushort4 o;
        o.x = __half_as_ushort(__float2half_rn(v.x));
        o.y = __half_as_ushort(__float2half_rn(v.y));
        o.z = __half_as_ushort(__float2half_rn(v.z));
        o.w = __half_as_ushort(__float2half_rn(v.w));
        ((ushort4*)g_wh)[i] = o;
    } else {
        int i = (blk - TR_BLOCKS - W_BLOCKS) * 256 + threadIdx.x;
        float4 v = ((const float4*)x)[i];
        ushort4 o;
        o.x = __half_as_ushort(__float2half_rn(v.x));
        o.y = __half_as_ushort(__float2half_rn(v.y));
        o.z = __half_as_ushort(__float2half_rn(v.z));
        o.w = __half_as_ushort(__float2half_rn(v.w));
        ((ushort4*)g_xh)[i] = o;
    }
}

// ---------------------------------------------------------------------------
// f16 1-pass GEMM via mma.sync (R10 best): curh = f16(Xh*Wh + bias).
// CTA 128x64 tile, 4 warps (2m x 2n), BK=64, 3 stages, 3 CTAs/SM.
// ---------------------------------------------------------------------------
#define BK       64
#define NCHUNK   (NI / BK)       // 8
#define NSTAGE   3
#define STAGE_B  (192 * 128)     // 24576
#define GEMM_SMEM (NSTAGE * STAGE_B)   // 73728

__global__ __launch_bounds__(128, 3) void gemm_tc(const float* __restrict__ bias) {
    extern __shared__ char smem[];
    uint32_t sb = smem_to_u32(smem);
    const int tid = threadIdx.x, lane = tid & 31, wid = tid >> 5;
    const int m0 = blockIdx.y * 128, n0 = blockIdx.x * 64;
    const int wm = (wid & 1) * 64;
    const int wn = (wid >> 1) * 32;

    float acc[4][4][4];
#pragma unroll
    for (int i = 0; i < 4; i++)
#pragma unroll
        for (int j = 0; j < 4; j++)
#pragma unroll
            for (int k = 0; k < 4; k++) acc[i][j][k] = 0.f;

    const __half* pA = g_xh + (size_t)(m0 + tid) * NI;
    const bool hasB = (tid < 64);
    const __half* pB = g_wh + (size_t)(n0 + (tid & 63)) * NI;
    const uint32_t rowA = (uint32_t)tid * 128;
    const uint32_t rowB = (uint32_t)(128 + tid) * 128;

    auto load_chunk = [&](int c) {
        uint32_t base = sb + (uint32_t)(c % NSTAGE) * STAGE_B;
#pragma unroll
        for (int j = 0; j < 8; j++)
            cp_async16(base + SWZ(rowA + j * 16), pA + c * BK + j * 8);
        if (hasB) {
#pragma unroll
            for (int j = 0; j < 8; j++)
                cp_async16(base + SWZ(rowB + j * 16), pB + c * BK + j * 8);
        }
        asm volatile("cp.async.commit_group;" ::: "memory");
    };

    const int a_row = wm + (lane & 15);
    const int a_cb  = (lane >> 4) * 16;
    const int b_row = 128 + wn + (lane & 7) + ((lane >> 4) * 8);
    const int b_cb  = ((lane >> 3) & 1) * 16;

    load_chunk(0);
    load_chunk(1);

    for (int c = 0; c < NCHUNK; c++) {
        asm volatile("cp.async.wait_group %0;" :: "n"(NSTAGE - 2) : "memory");
        __syncthreads();

        if (c + NSTAGE - 1 < NCHUNK) {
            load_chunk(c + NSTAGE - 1);
        } else {
            asm volatile("cp.async.commit_group;" ::: "memory");
        }

        uint32_t base = sb + (uint32_t)(c % NSTAGE) * STAGE_B;
#pragma unroll
        for (int kk = 0; kk < 4; kk++) {
            uint32_t ah[4][4], bh[4][2];
#pragma unroll
            for (int mt = 0; mt < 4; mt++) {
                uint32_t off = (uint32_t)((a_row + mt * 16) * 128 + kk * 32 + a_cb);
                ldsm_x4(ah[mt], base + SWZ(off));
            }
#pragma unroll
            for (int p = 0; p < 2; p++) {
                uint32_t off = (uint32_t)((b_row + p * 16) * 128 + kk * 32 + b_cb);
                uint32_t t4[4];
                ldsm_x4(t4, base + SWZ(off));
                bh[2 * p][0] = t4[0]; bh[2 * p][1] = t4[1];
                bh[2 * p + 1][0] = t4[2]; bh[2 * p + 1][1] = t4[3];
            }
#pragma unroll
            for (int mt = 0; mt < 4; mt++)
#pragma unroll
                for (int nt = 0; nt < 4; nt++)
                    mma16816f(acc[mt][nt], ah[mt], bh[nt]);
        }
    }

    const int erow = m0 + wm + (lane >> 2);
    const int ecol0 = n0 + wn + (lane & 3) * 2;
    float2 brg[4];
#pragma unroll
    for (int nt = 0; nt < 4; nt++)
        brg[nt] = *(const float2*)(bias + ecol0 + nt * 8);
#pragma unroll
    for (int mt = 0; mt < 4; mt++) {
        int r0 = erow + mt * 16;
#pragma unroll
        for (int nt = 0; nt < 4; nt++) {
            __half2 h0 = __floats2half2_rn(acc[mt][nt][0] + brg[nt].x,
                                           acc[mt][nt][1] + brg[nt].y);
            __half2 h1 = __floats2half2_rn(acc[mt][nt][2] + brg[nt].x,
                                           acc[mt][nt][3] + brg[nt].y);
            *(__half2*)(g_curh + (size_t)r0 * NN + ecol0 + nt * 8) = h0;
            *(__half2*)(g_curh + (size_t)(r0 + 8) * NN + ecol0 + nt * 8) = h1;
        }
    }
}

// ---------------------------------------------------------------------------
// ALIF scan: ONE CTA per batch (64 CTAs x 512 threads, 1 neuron/thread).
// cur is read once per batch (was twice with the 2-CTA stream split):
// 653MB total traffic vs 778MB. Speculative 8-step windows as before.
// ---------------------------------------------------------------------------
__global__ __launch_bounds__(512) void alif_scan(const float* __restrict__ beta,
                                                 const float* __restrict__ beta2,
                                                 const float* __restrict__ decay_v,
                                                 const float* __restrict__ decay_b,
                                                 float* __restrict__ out) {
    const int b = blockIdx.x;
    const int tid = threadIdx.x;
    const int w = tid >> 5, lane = tid & 31;

    __shared__ uint32_t zmask[16];
    __shared__ int act[NN];

    const float be = beta[tid];
    const float b2 = beta2[tid];
    const float dv = decay_v[tid];
    const float db = decay_b[tid];
    const float omdv = 1.f - dv;
    const float omdb = 1.f - db;

    float v = 0.f, bb = 0.f, zp = 0.f;
    int nact = 0;

    const __half* cur = g_curh + (size_t)b * NT * NN + tid;
    const float*  Rto = g_Rt + tid;

    float* zsb = out + (size_t)b * NT * NN + tid;
    float* vf  = out + ZS_ELEMS + (size_t)(0 * NB + b) * ST_STRIDE + tid;
    float* zf  = out + ZS_ELEMS + (size_t)(1 * NB + b) * ST_STRIDE + tid;
    float* bf  = out + ZS_ELEMS + (size_t)(2 * NB + b) * ST_STRIDE + tid;

    vf[0] = 0.f;
    zf[0] = 0.f;
    bf[0] = 0.f;

    __half cpre[8];
#pragma unroll
    for (int i = 0; i < 8; i++) cpre[i] = cur[(size_t)i * NN];

    auto slow_window = [&](int tb) {
        for (int u = 0; u < 8; u++) {
            const int t = tb + u;
            float c = __half2float(cur[(size_t)t * NN]);

            float rec = 0.f;
            for (int k = 0; k < nact; k++) rec += Rto[(size_t)act[k] * NN];

            v *= (1.f - zp);
            float vt = dv * v + omdv * ((c + rec) - bb);
            float zt = (vt >= 1.0f) ? 1.f : 0.f;
            bb = db * bb + omdb * (be * vt + b2 * zt);
            v = vt; zp = zt;

            size_t tpo = (size_t)(t + 1) * NN;
            zsb[(size_t)t * NN] = zt;
            vf[tpo] = vt;
            zf[tpo] = zt;
            bf[tpo] = bb;

            uint32_t m = __ballot_sync(0xffffffffu, zt != 0.f);
            if (lane == 0) zmask[w] = m;
            __syncthreads();
            int myoff = 0, tot = 0;
#pragma unroll
            for (int i = 0; i < 16; i++) {
                int pc = __popc(zmask[i]);
                if (i < w) myoff += pc;
                tot += pc;
            }
            if (zt != 0.f) {
                int rank = __popc(m & ((1u << lane) - 1u));
                act[myoff + rank] = tid;
            }
            nact = tot;
            __syncthreads();
        }
#pragma unroll
        for (int u = 0; u < 8; u++) {
            int tp = tb + 8 + u;
            if (tp < NT) cpre[u] = cur[(size_t)tp * NN];
        }
    };

    for (int tb = 0; tb < NT; tb += 8) {
        if (nact == 0) {
            const float v0 = v, bb0 = bb;
            int spec = 0;
#pragma unroll
            for (int u = 0; u < 8; u++) {
                const int t = tb + u;
                float c = __half2float(cpre[u]);
                if (t + 8 < NT) cpre[u] = cur[(size_t)(t + 8) * NN];

                float vt = dv * v + omdv * (c - bb);
                float zt = (vt >= 1.0f) ? 1.f : 0.f;
                spec |= (zt != 0.f);
                bb = db * bb + omdb * (be * vt + b2 * zt);
                v = vt;

                size_t tpo = (size_t)(t + 1) * NN;
                zsb[(size_t)t * NN] = zt;
                vf[tpo] = vt;
                zf[tpo] = zt;
                bf[tpo] = bb;
            }
            int flag = __syncthreads_count(spec);
            if (flag) {
                v = v0; bb = bb0; zp = 0.f; nact = 0;
                slow_window(tb);
            } else {
                zp = 0.f; nact = 0;
            }
        } else {
            slow_window(tb);
        }
    }
}

// ---------------------------------------------------------------------------
extern "C" void kernel_launch(void* const* d_in, const int* in_sizes, int n_in,
                              void* d_out, int out_size) {
    const float* x     = (const float*)d_in[0];
    const float* W     = (const float*)d_in[1];
    const float* bias  = (const float*)d_in[2];
    const float* R     = (const float*)d_in[3];
    const float* beta  = (const float*)d_in[4];
    const float* beta2 = (const float*)d_in[5];
    const float* dvp   = (const float*)d_in[6];
    const float* dbp   = (const float*)d_in[7];
    float* out = (float*)d_out;

    cudaFuncSetAttribute(gemm_tc, cudaFuncAttributeMaxDynamicSharedMemorySize, GEMM_SMEM);

    prep_all<<<TR_BLOCKS + W_BLOCKS + X_BLOCKS, 256>>>(R, W, x);

    dim3 ggrid(NN / 64, NM / 128);   // (8, 500), n fastest
    gemm_tc<<<ggrid, 128, GEMM_SMEM>>>(bias);

    alif_scan<<<NB, 512>>>(beta, beta2, dvp, dbp, out);
}

// round 16
// speedup vs baseline: 1.4583x; 1.0532x over previous
#include <cuda_runtime.h>
#include <cuda_bf16.h>
#include <cuda_fp16.h>
#include <cstdint>

// Problem constants
#define NB   64
#define NT   1000
#define NN   512
#define NI   512
#define NM   (NB*NT)

#define ZS_ELEMS   (NB*NT*NN)
#define ST_STRIDE  ((NT+1)*NN)

// ---------------------------------------------------------------------------
// Scratch (device globals — no allocation allowed)
// g_curh layout: row m = b*NT + t
// ---------------------------------------------------------------------------
__device__ __align__(16) __half g_curh[(size_t)NM * NN];
__device__ float  g_Rt[NN * NN];
__device__ __align__(16) __half g_xh[(size_t)NM * NI];
__device__ __align__(16) __half g_wh[NN * NI];

// ---------------------------------------------------------------------------
// Portable PTX helpers (sm_80+ only — tcgen05 unavailable at compute_103)
// ---------------------------------------------------------------------------
__device__ __forceinline__ uint32_t smem_to_u32(const void* p) {
    uint32_t a;
    asm("{ .reg .u64 t; cvta.to.shared.u64 t, %1; cvt.u32.u64 %0, t; }" : "=r"(a) : "l"(p));
    return a;
}
__device__ __forceinline__ void cp_async16(uint32_t dst, const void* src) {
    asm volatile("cp.async.cg.shared.global [%0], [%1], 16;" :: "r"(dst), "l"(src) : "memory");
}
__device__ __forceinline__ void ldsm_x4(uint32_t r[4], uint32_t addr) {
    asm volatile("ldmatrix.sync.aligned.m8n8.x4.shared.b16 {%0,%1,%2,%3}, [%4];"
        : "=r"(r[0]), "=r"(r[1]), "=r"(r[2]), "=r"(r[3]) : "r"(addr));
}
__device__ __forceinline__ void mma16816f(float d[4], const uint32_t a[4], const uint32_t b[2]) {
    asm volatile("mma.sync.aligned.m16n8k16.row.col.f32.f16.f16.f32 "
        "{%0,%1,%2,%3}, {%4,%5,%6,%7}, {%8,%9}, {%0,%1,%2,%3};"
        : "+f"(d[0]), "+f"(d[1]), "+f"(d[2]), "+f"(d[3])
        : "r"(a[0]), "r"(a[1]), "r"(a[2]), "r"(a[3]), "r"(b[0]), "r"(b[1]));
}
#define SWZ(off) ((off) ^ (((off) >> 3) & 0x70))

// ---------------------------------------------------------------------------
// prep_all: transpose R + convert W -> f16 + convert x -> f16.
// ---------------------------------------------------------------------------
#define TR_BLOCKS 256
#define W_BLOCKS  ((NN * NI / 4) / 256)  // 256
#define X_BLOCKS  ((NM * NI / 4) / 256)  // 32768
__global__ __launch_bounds__(256) void prep_all(const float* __restrict__ R,
                                                const float* __restrict__ W,
                                                const float* __restrict__ x) {
    int blk = blockIdx.x;
    if (blk < TR_BLOCKS) {
        __shared__ float tile[32][33];
        int bx = (blk & 15) * 32, by = (blk >> 4) * 32;
        int tx = threadIdx.x & 31, ty8 = threadIdx.x >> 5;
#pragma unroll
        for (int r = 0; r < 4; r++) {
            int y = ty8 + r * 8;
            tile[y][tx] = R[(by + y) * NN + bx + tx];
        }
        __syncthreads();
#pragma unroll
        for (int r = 0; r < 4; r++) {
            int y = ty8 + r * 8;
            g_Rt[(bx + y) * NN + (by + tx)] = tile[tx][y];
        }
    } else if (blk < TR_BLOCKS + W_BLOCKS) {
        int i = (blk - TR_BLOCKS) * 256 + threadIdx.x;
        float4 v = ((const float4*)W)[i];
        ushort4 o;
        o.x = __half_as_ushort(__float2half_rn(v.x));
        o.y = __half_as_ushort(__float2half_rn(v.y));
        o.z = __half_as_ushort(__float2half_rn(v.z));
        o.w = __half_as_ushort(__float2half_rn(v.w));
        ((ushort4*)g_wh)[i] = o;
    } else {
        int i = (blk - TR_BLOCKS - W_BLOCKS) * 256 + threadIdx.x;
        float4 v = ((const float4*)x)[i];
        ushort4 o;
        o.x = __half_as_ushort(__float2half_rn(v.x));
        o.y = __half_as_ushort(__float2half_rn(v.y));
        o.z = __half_as_ushort(__float2half_rn(v.z));
        o.w = __half_as_ushort(__float2half_rn(v.w));
        ((ushort4*)g_xh)[i] = o;
    }
}

// ---------------------------------------------------------------------------
// f16 1-pass GEMM via mma.sync (R10 best): curh = f16(Xh*Wh + bias).
// CTA 128x64 tile, 4 warps (2m x 2n), BK=64, 3 stages, 3 CTAs/SM.
// ---------------------------------------------------------------------------
#define BK       64
#define NCHUNK   (NI / BK)       // 8
#define NSTAGE   3
#define STAGE_B  (192 * 128)     // 24576
#define GEMM_SMEM (NSTAGE * STAGE_B)   // 73728

__global__ __launch_bounds__(128, 3) void gemm_tc(const float* __restrict__ bias) {
    extern __shared__ char smem[];
    uint32_t sb = smem_to_u32(smem);
    const int tid = threadIdx.x, lane = tid & 31, wid = tid >> 5;
    const int m0 = blockIdx.y * 128, n0 = blockIdx.x * 64;
    const int wm = (wid & 1) * 64;
    const int wn = (wid >> 1) * 32;

    float acc[4][4][4];
#pragma unroll
    for (int i = 0; i < 4; i++)
#pragma unroll
        for (int j = 0; j < 4; j++)
#pragma unroll
            for (int k = 0; k < 4; k++) acc[i][j][k] = 0.f;

    const __half* pA = g_xh + (size_t)(m0 + tid) * NI;
    const bool hasB = (tid < 64);
    const __half* pB = g_wh + (size_t)(n0 + (tid & 63)) * NI;
    const uint32_t rowA = (uint32_t)tid * 128;
    const uint32_t rowB = (uint32_t)(128 + tid) * 128;

    auto load_chunk = [&](int c) {
        uint32_t base = sb + (uint32_t)(c % NSTAGE) * STAGE_B;
#pragma unroll
        for (int j = 0; j < 8; j++)
            cp_async16(base + SWZ(rowA + j * 16), pA + c * BK + j * 8);
        if (hasB) {
#pragma unroll
            for (int j = 0; j < 8; j++)
                cp_async16(base + SWZ(rowB + j * 16), pB + c * BK + j * 8);
        }
        asm volatile("cp.async.commit_group;" ::: "memory");
    };

    const int a_row = wm + (lane & 15);
    const int a_cb  = (lane >> 4) * 16;
    const int b_row = 128 + wn + (lane & 7) + ((lane >> 4) * 8);
    const int b_cb  = ((lane >> 3) & 1) * 16;

    load_chunk(0);
    load_chunk(1);

    for (int c = 0; c < NCHUNK; c++) {
        asm volatile("cp.async.wait_group %0;" :: "n"(NSTAGE - 2) : "memory");
        __syncthreads();

        if (c + NSTAGE - 1 < NCHUNK) {
            load_chunk(c + NSTAGE - 1);
        } else {
            asm volatile("cp.async.commit_group;" ::: "memory");
        }

        uint32_t base = sb + (uint32_t)(c % NSTAGE) * STAGE_B;
#pragma unroll
        for (int kk = 0; kk < 4; kk++) {
            uint32_t ah[4][4], bh[4][2];
#pragma unroll
            for (int mt = 0; mt < 4; mt++) {
                uint32_t off = (uint32_t)((a_row + mt * 16) * 128 + kk * 32 + a_cb);
                ldsm_x4(ah[mt], base + SWZ(off));
            }
#pragma unroll
            for (int p = 0; p < 2; p++) {
                uint32_t off = (uint32_t)((b_row + p * 16) * 128 + kk * 32 + b_cb);
                uint32_t t4[4];
                ldsm_x4(t4, base + SWZ(off));
                bh[2 * p][0] = t4[0]; bh[2 * p][1] = t4[1];
                bh[2 * p + 1][0] = t4[2]; bh[2 * p + 1][1] = t4[3];
            }
#pragma unroll
            for (int mt = 0; mt < 4; mt++)
#pragma unroll
                for (int nt = 0; nt < 4; nt++)
                    mma16816f(acc[mt][nt], ah[mt], bh[nt]);
        }
    }

    const int erow = m0 + wm + (lane >> 2);
    const int ecol0 = n0 + wn + (lane & 3) * 2;
    float2 brg[4];
#pragma unroll
    for (int nt = 0; nt < 4; nt++)
        brg[nt] = *(const float2*)(bias + ecol0 + nt * 8);
#pragma unroll
    for (int mt = 0; mt < 4; mt++) {
        int r0 = erow + mt * 16;
#pragma unroll
        for (int nt = 0; nt < 4; nt++) {
            __half2 h0 = __floats2half2_rn(acc[mt][nt][0] + brg[nt].x,
                                           acc[mt][nt][1] + brg[nt].y);
            __half2 h1 = __floats2half2_rn(acc[mt][nt][2] + brg[nt].x,
                                           acc[mt][nt][3] + brg[nt].y);
            *(__half2*)(g_curh + (size_t)r0 * NN + ecol0 + nt * 8) = h0;
            *(__half2*)(g_curh + (size_t)(r0 + 8) * NN + ecol0 + nt * 8) = h1;
        }
    }
}

// ---------------------------------------------------------------------------
// ALIF scan (R10 shape): 128 CTAs (2 per batch, stream-split), 512 threads,
// 1 neuron/thread, speculative 8-step windows.
// NEW: all output stores use __stcs (streaming, evict-first) — outputs are
// never re-read, so keep L2 for the cur stream the partner CTA re-reads.
// ---------------------------------------------------------------------------
__global__ __launch_bounds__(512) void alif_scan(const float* __restrict__ beta,
                                                 const float* __restrict__ beta2,
                                                 const float* __restrict__ decay_v,
                                                 const float* __restrict__ decay_b,
                                                 float* __restrict__ out) {
    const int b = blockIdx.x >> 1;
    const int p = blockIdx.x & 1;
    const int tid = threadIdx.x;
    const int w = tid >> 5, lane = tid & 31;

    __shared__ uint32_t zmask[16];
    __shared__ int act[NN];

    const float be = beta[tid];
    const float b2 = beta2[tid];
    const float dv = decay_v[tid];
    const float db = decay_b[tid];
    const float omdv = 1.f - dv;
    const float omdb = 1.f - db;

    float v = 0.f, bb = 0.f, zp = 0.f;
    int nact = 0;

    const __half* cur = g_curh + (size_t)b * NT * NN + tid;
    const float*  Rto = g_Rt + tid;

    float* zsb = out + (size_t)b * NT * NN + tid;
    float* vf  = out + ZS_ELEMS + (size_t)(0 * NB + b) * ST_STRIDE + tid;
    float* zf  = out + ZS_ELEMS + (size_t)(1 * NB + b) * ST_STRIDE + tid;
    float* bf  = out + ZS_ELEMS + (size_t)(2 * NB + b) * ST_STRIDE + tid;

    if (p == 0) {
        __stcs(vf, 0.f);
    } else {
        __stcs(zf, 0.f);
        __stcs(bf, 0.f);
    }

    __half cpre[8];
#pragma unroll
    for (int i = 0; i < 8; i++) cpre[i] = cur[(size_t)i * NN];

    auto slow_window = [&](int tb) {
        for (int u = 0; u < 8; u++) {
            const int t = tb + u;
            float c = __half2float(cur[(size_t)t * NN]);

            float rec = 0.f;
            for (int k = 0; k < nact; k++) rec += Rto[(size_t)act[k] * NN];

            v *= (1.f - zp);
            float vt = dv * v + omdv * ((c + rec) - bb);
            float zt = (vt >= 1.0f) ? 1.f : 0.f;
            bb = db * bb + omdb * (be * vt + b2 * zt);
            v = vt; zp = zt;

            size_t tpo = (size_t)(t + 1) * NN;
            if (p == 0) {
                __stcs(zsb + (size_t)t * NN, zt);
                __stcs(vf + tpo, vt);
            } else {
                __stcs(zf + tpo, zt);
                __stcs(bf + tpo, bb);
            }

            uint32_t m = __ballot_sync(0xffffffffu, zt != 0.f);
            if (lane == 0) zmask[w] = m;
            __syncthreads();
            int myoff = 0, tot = 0;
#pragma unroll
            for (int i = 0; i < 16; i++) {
                int pc = __popc(zmask[i]);
                if (i < w) myoff += pc;
                tot += pc;
            }
            if (zt != 0.f) {
                int rank = __popc(m & ((1u << lane) - 1u));
                act[myoff + rank] = tid;
            }
            nact = tot;
            __syncthreads();
        }
#pragma unroll
        for (int u = 0; u < 8; u++) {
            int tp = tb + 8 + u;
            if (tp < NT) cpre[u] = cur[(size_t)tp * NN];
        }
    };

    for (int tb = 0; tb < NT; tb += 8) {
        if (nact == 0) {
            const float v0 = v, bb0 = bb;
            int spec = 0;
#pragma unroll
            for (int u = 0; u < 8; u++) {
                const int t = tb + u;
                float c = __half2float(cpre[u]);
                if (t + 8 < NT) cpre[u] = cur[(size_t)(t + 8) * NN];

                float vt = dv * v + omdv * (c - bb);
                float zt = (vt >= 1.0f) ? 1.f : 0.f;
                spec |= (zt != 0.f);
                bb = db * bb + omdb * (be * vt + b2 * zt);
                v = vt;

                size_t tpo = (size_t)(t + 1) * NN;
                if (p == 0) {
                    __stcs(zsb + (size_t)t * NN, zt);
                    __stcs(vf + tpo, vt);
                } else {
                    __stcs(zf + tpo, zt);
                    __stcs(bf + tpo, bb);
                }
            }
            int flag = __syncthreads_count(spec);
            if (flag) {
                v = v0; bb = bb0; zp = 0.f; nact = 0;
                slow_window(tb);
            } else {
                zp = 0.f; nact = 0;
            }
        } else {
            slow_window(tb);
        }
    }
}

// ---------------------------------------------------------------------------
extern "C" void kernel_launch(void* const* d_in, const int* in_sizes, int n_in,
                              void* d_out, int out_size) {
    const float* x     = (const float*)d_in[0];
    const float* W     = (const float*)d_in[1];
    const float* bias  = (const float*)d_in[2];
    const float* R     = (const float*)d_in[3];
    const float* beta  = (const float*)d_in[4];
    const float* beta2 = (const float*)d_in[5];
    const float* dvp   = (const float*)d_in[6];
    const float* dbp   = (const float*)d_in[7];
    float* out = (float*)d_out;

    cudaFuncSetAttribute(gemm_tc, cudaFuncAttributeMaxDynamicSharedMemorySize, GEMM_SMEM);

    prep_all<<<TR_BLOCKS + W_BLOCKS + X_BLOCKS, 256>>>(R, W, x);

    dim3 ggrid(NN / 64, NM / 128);   // (8, 500), n fastest
    gemm_tc<<<ggrid, 128, GEMM_SMEM>>>(bias);

    alif_scan<<<2 * NB, 512>>>(beta, beta2, dvp, dbp, out);
}

// round 17
// speedup vs baseline: 1.5657x; 1.0737x over previous
#include <cuda_runtime.h>
#include <cuda_bf16.h>
#include <cuda_fp16.h>
#include <cstdint>

// Problem constants
#define NB   64
#define NT   1000
#define NN   512
#define NI   512
#define NM   (NB*NT)

#define ZS_ELEMS   (NB*NT*NN)
#define ST_STRIDE  ((NT+1)*NN)

// ---------------------------------------------------------------------------
// Scratch (device globals — no allocation allowed)
// g_curh layout: row m = b*NT + t
// ---------------------------------------------------------------------------
__device__ __align__(16) __half g_curh[(size_t)NM * NN];
__device__ float  g_Rt[NN * NN];
__device__ __align__(16) __half g_xh[(size_t)NM * NI];
__device__ __align__(16) __half g_wh[NN * NI];

// ---------------------------------------------------------------------------
// Portable PTX helpers (sm_80+ only — tcgen05 unavailable at compute_103)
// ---------------------------------------------------------------------------
__device__ __forceinline__ uint32_t smem_to_u32(const void* p) {
    uint32_t a;
    asm("{ .reg .u64 t; cvta.to.shared.u64 t, %1; cvt.u32.u64 %0, t; }" : "=r"(a) : "l"(p));
    return a;
}
__device__ __forceinline__ void cp_async16(uint32_t dst, const void* src) {
    asm volatile("cp.async.cg.shared.global [%0], [%1], 16;" :: "r"(dst), "l"(src) : "memory");
}
__device__ __forceinline__ void ldsm_x4(uint32_t r[4], uint32_t addr) {
    asm volatile("ldmatrix.sync.aligned.m8n8.x4.shared.b16 {%0,%1,%2,%3}, [%4];"
        : "=r"(r[0]), "=r"(r[1]), "=r"(r[2]), "=r"(r[3]) : "r"(addr));
}
__device__ __forceinline__ void mma16816f(float d[4], const uint32_t a[4], const uint32_t b[2]) {
    asm volatile("mma.sync.aligned.m16n8k16.row.col.f32.f16.f16.f32 "
        "{%0,%1,%2,%3}, {%4,%5,%6,%7}, {%8,%9}, {%0,%1,%2,%3};"
        : "+f"(d[0]), "+f"(d[1]), "+f"(d[2]), "+f"(d[3])
        : "r"(a[0]), "r"(a[1]), "r"(a[2]), "r"(a[3]), "r"(b[0]), "r"(b[1]));
}
#define SWZ(off) ((off) ^ (((off) >> 3) & 0x70))

// ---------------------------------------------------------------------------
// prep_all: transpose R + convert W -> f16 + convert x -> f16.
// ---------------------------------------------------------------------------
#define TR_BLOCKS 256
#define W_BLOCKS  ((NN * NI / 4) / 256)  // 256
#define X_BLOCKS  ((NM * NI / 4) / 256)  // 32768
__global__ __launch_bounds__(256) void prep_all(const float* __restrict__ R,
                                                const float* __restrict__ W,
                                                const float* __restrict__ x) {
    int blk = blockIdx.x;
    if (blk < TR_BLOCKS) {
        __shared__ float tile[32][33];
        int bx = (blk & 15) * 32, by = (blk >> 4) * 32;
        int tx = threadIdx.x & 31, ty8 = threadIdx.x >> 5;
#pragma unroll
        for (int r = 0; r < 4; r++) {
            int y = ty8 + r * 8;
            tile[y][tx] = R[(by + y) * NN + bx + tx];
        }
        __syncthreads();
#pragma unroll
        for (int r = 0; r < 4; r++) {
            int y = ty8 + r * 8;
            g_Rt[(bx + y) * NN + (by + tx)] = tile[tx][y];
        }
    } else if (blk < TR_BLOCKS + W_BLOCKS) {
        int i = (blk - TR_BLOCKS) * 256 + threadIdx.x;
        float4 v = ((const float4*)W)[i];
        ushort4 o;
        o.x = __half_as_ushort(__float2half_rn(v.x));
        o.y = __half_as_ushort(__float2half_rn(v.y));
        o.z = __half_as_ushort(__float2half_rn(v.z));
        o.w = __half_as_ushort(__float2half_rn(v.w));
        ((ushort4*)g_wh)[i] = o;
    } else {
        int i = (blk - TR_BLOCKS - W_BLOCKS) * 256 + threadIdx.x;
        float4 v = ((const float4*)x)[i];
        ushort4 o;
        o.x = __half_as_ushort(__float2half_rn(v.x));
        o.y = __half_as_ushort(__float2half_rn(v.y));
        o.z = __half_as_ushort(__float2half_rn(v.z));
        o.w = __half_as_ushort(__float2half_rn(v.w));
        ((ushort4*)g_xh)[i] = o;
    }
}

// ---------------------------------------------------------------------------
// f16 1-pass GEMM via mma.sync: curh = f16(Xh*Wh + bias).
// CTA 128x128 tile, 4 warps (2m x 2n), warp tile 64x64, BK=64, 3 stages.
// 8 LDSM per 32 MMAs per k16 (was 6 per 16) — halves the per-MMA fixed
// overhead that limited the 1-pass GEMM to 68% of the HMMA rate ceiling.
// Stage (32KB): 256 rows x 128B; rows 0-127 = A(xh), 128-255 = Wh.
// 96KB smem + ~190 regs -> 2 CTAs/SM.
// ---------------------------------------------------------------------------
#define BK       64
#define NCHUNK   (NI / BK)       // 8
#define NSTAGE   3
#define STAGE_B  (256 * 128)     // 32768
#define GEMM_SMEM (NSTAGE * STAGE_B)   // 98304

__global__ __launch_bounds__(128, 2) void gemm_tc(const float* __restrict__ bias) {
    extern __shared__ char smem[];
    uint32_t sb = smem_to_u32(smem);
    const int tid = threadIdx.x, lane = tid & 31, wid = tid >> 5;
    const int m0 = blockIdx.y * 128, n0 = blockIdx.x * 128;
    const int wm = (wid & 1) * 64;
    const int wn = (wid >> 1) * 64;

    float acc[4][8][4];
#pragma unroll
    for (int i = 0; i < 4; i++)
#pragma unroll
        for (int j = 0; j < 8; j++)
#pragma unroll
            for (int k = 0; k < 4; k++) acc[i][j][k] = 0.f;

    // loader: thread t owns A row t AND B row 128+t
    const __half* pA = g_xh + (size_t)(m0 + tid) * NI;
    const __half* pB = g_wh + (size_t)(n0 + tid) * NI;
    const uint32_t rowA = (uint32_t)tid * 128;
    const uint32_t rowB = (uint32_t)(128 + tid) * 128;

    auto load_chunk = [&](int c) {
        uint32_t base = sb + (uint32_t)(c % NSTAGE) * STAGE_B;
#pragma unroll
        for (int j = 0; j < 8; j++)
            cp_async16(base + SWZ(rowA + j * 16), pA + c * BK + j * 8);
#pragma unroll
        for (int j = 0; j < 8; j++)
            cp_async16(base + SWZ(rowB + j * 16), pB + c * BK + j * 8);
        asm volatile("cp.async.commit_group;" ::: "memory");
    };

    const int a_row = wm + (lane & 15);
    const int a_cb  = (lane >> 4) * 16;
    const int b_row = 128 + wn + (lane & 7) + ((lane >> 4) * 8);
    const int b_cb  = ((lane >> 3) & 1) * 16;

    load_chunk(0);
    load_chunk(1);

    for (int c = 0; c < NCHUNK; c++) {
        asm volatile("cp.async.wait_group %0;" :: "n"(NSTAGE - 2) : "memory");
        __syncthreads();

        if (c + NSTAGE - 1 < NCHUNK) {
            load_chunk(c + NSTAGE - 1);
        } else {
            asm volatile("cp.async.commit_group;" ::: "memory");
        }

        uint32_t base = sb + (uint32_t)(c % NSTAGE) * STAGE_B;
#pragma unroll
        for (int kk = 0; kk < 4; kk++) {
            uint32_t ah[4][4], bh[8][2];
#pragma unroll
            for (int mt = 0; mt < 4; mt++) {
                uint32_t off = (uint32_t)((a_row + mt * 16) * 128 + kk * 32 + a_cb);
                ldsm_x4(ah[mt], base + SWZ(off));
            }
#pragma unroll
            for (int p = 0; p < 4; p++) {
                uint32_t off = (uint32_t)((b_row + p * 16) * 128 + kk * 32 + b_cb);
                uint32_t t4[4];
                ldsm_x4(t4, base + SWZ(off));
                bh[2 * p][0] = t4[0]; bh[2 * p][1] = t4[1];
                bh[2 * p + 1][0] = t4[2]; bh[2 * p + 1][1] = t4[3];
            }
            // pass-major: consecutive MMAs hit different accumulators
#pragma unroll
            for (int mt = 0; mt < 4; mt++)
#pragma unroll
                for (int nt = 0; nt < 8; nt++)
                    mma16816f(acc[mt][nt], ah[mt], bh[nt]);
        }
    }

    // Epilogue: +bias, convert to f16, store half2
    const int erow = m0 + wm + (lane >> 2);
    const int ecol0 = n0 + wn + (lane & 3) * 2;
    float2 brg[8];
#pragma unroll
    for (int nt = 0; nt < 8; nt++)
        brg[nt] = *(const float2*)(bias + ecol0 + nt * 8);
#pragma unroll
    for (int mt = 0; mt < 4; mt++) {
        int r0 = erow + mt * 16;
#pragma unroll
        for (int nt = 0; nt < 8; nt++) {
            __half2 h0 = __floats2half2_rn(acc[mt][nt][0] + brg[nt].x,
                                           acc[mt][nt][1] + brg[nt].y);
            __half2 h1 = __floats2half2_rn(acc[mt][nt][2] + brg[nt].x,
                                           acc[mt][nt][3] + brg[nt].y);
            *(__half2*)(g_curh + (size_t)r0 * NN + ecol0 + nt * 8) = h0;
            *(__half2*)(g_curh + (size_t)(r0 + 8) * NN + ecol0 + nt * 8) = h1;
        }
    }
}

// ---------------------------------------------------------------------------
// ALIF scan (R10 best): 128 CTAs (2 per batch, stream-split), 512 threads,
// 1 neuron/thread, speculative 8-step windows, ballot path on spikes.
// ---------------------------------------------------------------------------
__global__ __launch_bounds__(512) void alif_scan(const float* __restrict__ beta,
                                                 const float* __restrict__ beta2,
                                                 const float* __restrict__ decay_v,
                                                 const float* __restrict__ decay_b,
                                                 float* __restrict__ out) {
    const int b = blockIdx.x >> 1;
    const int p = blockIdx.x & 1;
    const int tid = threadIdx.x;
    const int w = tid >> 5, lane = tid & 31;

    __shared__ uint32_t zmask[16];
    __shared__ int act[NN];

    const float be = beta[tid];
    const float b2 = beta2[tid];
    const float dv = decay_v[tid];
    const float db = decay_b[tid];
    const float omdv = 1.f - dv;
    const float omdb = 1.f - db;

    float v = 0.f, bb = 0.f, zp = 0.f;
    int nact = 0;

    const __half* cur = g_curh + (size_t)b * NT * NN + tid;
    const float*  Rto = g_Rt + tid;

    float* zsb = out + (size_t)b * NT * NN + tid;
    float* vf  = out + ZS_ELEMS + (size_t)(0 * NB + b) * ST_STRIDE + tid;
    float* zf  = out + ZS_ELEMS + (size_t)(1 * NB + b) * ST_STRIDE + tid;
    float* bf  = out + ZS_ELEMS + (size_t)(2 * NB + b) * ST_STRIDE + tid;

    if (p == 0) {
        vf[0] = 0.f;
    } else {
        zf[0] = 0.f;
        bf[0] = 0.f;
    }

    __half cpre[8];
#pragma unroll
    for (int i = 0; i < 8; i++) cpre[i] = cur[(size_t)i * NN];

    auto slow_window = [&](int tb) {
        for (int u = 0; u < 8; u++) {
            const int t = tb + u;
            float c = __half2float(cur[(size_t)t * NN]);

            float rec = 0.f;
            for (int k = 0; k < nact; k++) rec += Rto[(size_t)act[k] * NN];

            v *= (1.f - zp);
            float vt = dv * v + omdv * ((c + rec) - bb);
            float zt = (vt >= 1.0f) ? 1.f : 0.f;
            bb = db * bb + omdb * (be * vt + b2 * zt);
            v = vt; zp = zt;

            size_t tpo = (size_t)(t + 1) * NN;
            if (p == 0) {
                zsb[(size_t)t * NN] = zt;
                vf[tpo] = vt;
            } else {
                zf[tpo] = zt;
                bf[tpo] = bb;
            }

            uint32_t m = __ballot_sync(0xffffffffu, zt != 0.f);
            if (lane == 0) zmask[w] = m;
            __syncthreads();
            int myoff = 0, tot = 0;
#pragma unroll
            for (int i = 0; i < 16; i++) {
                int pc = __popc(zmask[i]);
                if (i < w) myoff += pc;
                tot += pc;
            }
            if (zt != 0.f) {
                int rank = __popc(m & ((1u << lane) - 1u));
                act[myoff + rank] = tid;
            }
            nact = tot;
            __syncthreads();
        }
#pragma unroll
        for (int u = 0; u < 8; u++) {
            int tp = tb + 8 + u;
            if (tp < NT) cpre[u] = cur[(size_t)tp * NN];
        }
    };

    for (int tb = 0; tb < NT; tb += 8) {
        if (nact == 0) {
            const float v0 = v, bb0 = bb;
            int spec = 0;
#pragma unroll
            for (int u = 0; u < 8; u++) {
                const int t = tb + u;
                float c = __half2float(cpre[u]);
                if (t + 8 < NT) cpre[u] = cur[(size_t)(t + 8) * NN];

                float vt = dv * v + omdv * (c - bb);
                float zt = (vt >= 1.0f) ? 1.f : 0.f;
                spec |= (zt != 0.f);
                bb = db * bb + omdb * (be * vt + b2 * zt);
                v = vt;

                size_t tpo = (size_t)(t + 1) * NN;
                if (p == 0) {
                    zsb[(size_t)t * NN] = zt;
                    vf[tpo] = vt;
                } else {
                    zf[tpo] = zt;
                    bf[tpo] = bb;
                }
            }
            int flag = __syncthreads_count(spec);
            if (flag) {
                v = v0; bb = bb0; zp = 0.f; nact = 0;
                slow_window(tb);
            } else {
                zp = 0.f; nact = 0;
            }
        } else {
            slow_window(tb);
        }
    }
}

// ---------------------------------------------------------------------------
extern "C" void kernel_launch(void* const* d_in, const int* in_sizes, int n_in,
                              void* d_out, int out_size) {
    const float* x     = (const float*)d_in[0];
    const float* W     = (const float*)d_in[1];
    const float* bias  = (const float*)d_in[2];
    const float* R     = (const float*)d_in[3];
    const float* beta  = (const float*)d_in[4];
    const float* beta2 = (const float*)d_in[5];
    const float* dvp   = (const float*)d_in[6];
    const float* dbp   = (const float*)d_in[7];
    float* out = (float*)d_out;

    cudaFuncSetAttribute(gemm_tc, cudaFuncAttributeMaxDynamicSharedMemorySize, GEMM_SMEM);

    prep_all<<<TR_BLOCKS + W_BLOCKS + X_BLOCKS, 256>>>(R, W, x);

    dim3 ggrid(NN / 128, NM / 128);   // (4, 500), n fastest
    gemm_tc<<<ggrid, 128, GEMM_SMEM>>>(bias);

    alif_scan<<<2 * NB, 512>>>(beta, beta2, dvp, dbp, out);
}